// round 10
// baseline (speedup 1.0000x reference)
#include <cuda_runtime.h>
#include <cuda_fp16.h>
#include <cstdint>

// Input [32, 512, 512, 3] float32 NHWC, 3x3 median, replicate border.
constexpr int Bn  = 32;
constexpr int H   = 512;
constexpr int W   = 512;
constexpr int C   = 3;
constexpr int ROW = W * C;             // 1536 floats per image row
constexpr int IMG = H * ROW;
constexpr int EPT = 8;                 // wc outputs per thread per row
constexpr int TPR = ROW / EPT;         // 192 slots per row
constexpr int PPT = 8;                 // row-pairs per thread (16 output rows)
constexpr int GROUPS = (H / 2) / PPT;  // 32 pair-groups per image
constexpr int BLOCK = 64;

// Interior kernel: slots 1..190 (wc0 = 8 .. ROW-16)
constexpr int TPR_I = TPR - 2;                 // 190
constexpr int NTH_I = Bn * GROUPS * TPR_I;     // 194,560
// Edge kernel: slots {0, 191}
constexpr int NTH_E = Bn * GROUPS * 2;         // 2,048

__device__ __forceinline__ __half2 med3h2(__half2 a, __half2 b, __half2 c) {
    __half2 mn = __hmin2(a, b);
    __half2 mx = __hmax2(a, b);
    return __hmax2(mn, __hmin2(mx, c));
}
// (a.high16 | b.low16) — one PRMT
__device__ __forceinline__ __half2 prmt_h2(__half2 a, __half2 b) {
    unsigned int au = *reinterpret_cast<unsigned int*>(&a);
    unsigned int bu = *reinterpret_cast<unsigned int*>(&b);
    unsigned int r  = __byte_perm(au, bu, 0x5432);
    return *reinterpret_cast<__half2*>(&r);
}

__device__ __forceinline__ void load_raw(const float* __restrict__ r, int base,
                                         float4 t[4]) {
    const float4* p = reinterpret_cast<const float4*>(r + base);
    t[0] = p[0]; t[1] = p[1]; t[2] = p[2]; t[3] = p[3];
}
__device__ __forceinline__ void to_arr(const float4 t4[4], float w[16]) {
    w[0]=t4[0].x; w[1]=t4[0].y; w[2]=t4[0].z; w[3]=t4[0].w;
    w[4]=t4[1].x; w[5]=t4[1].y; w[6]=t4[1].z; w[7]=t4[1].w;
    w[8]=t4[2].x; w[9]=t4[2].y; w[10]=t4[2].z; w[11]=t4[2].w;
    w[12]=t4[3].x; w[13]=t4[3].y; w[14]=t4[3].z; w[15]=t4[3].w;
}
// Edge-replicate remap (edge kernel only).
__device__ __forceinline__ void remap(const float4 t4[4], int mode, float w[16]) {
    float t[16];
    to_arr(t4, t);
    if (mode == 1) {
        w[0] = t[0]; w[1] = t[0]; w[2] = t[1]; w[3] = t[2];
        #pragma unroll
        for (int k = 4; k < 16; k++) w[k] = t[k - 4];
    } else {
        #pragma unroll
        for (int k = 0; k < 12; k++) w[k] = t[k + 4];
        w[12] = t[13]; w[13] = t[14]; w[14] = t[15]; w[15] = t[15];
    }
}

// Column sorts + pair-shared horizontal combine + streaming store of one row pair.
__device__ __forceinline__ void process_store(const __half2* x, const __half2* y,
                                              const __half2* z, float* o) {
    __half2 mn[15], md[15], mx[15];
    #pragma unroll
    for (int k = 1; k <= 14; k++) {
        __half2 lo2 = __hmin2(y[k], z[k]);
        __half2 hi2 = __hmax2(y[k], z[k]);
        mn[k] = __hmin2(x[k], lo2);
        mx[k] = __hmax2(x[k], hi2);
        md[k] = __hmax2(lo2, __hmin2(x[k], hi2));
    }
    __half2 qlo[9], qhi[9], qa[9], qb[9];
    #pragma unroll
    for (int k = 4; k <= 8; k++) {
        qlo[k] = __hmax2(mn[k], mn[k + 3]);
        qhi[k] = __hmin2(mx[k], mx[k + 3]);
        qa[k]  = __hmin2(md[k], md[k + 3]);
        qb[k]  = __hmax2(md[k], md[k + 3]);
    }
    float r0[EPT], r1[EPT];
    #pragma unroll
    for (int j = 0; j < EPT; j++) {
        int kp = (j < 4) ? (j + 4) : (j + 1);
        int ks = (j < 4) ? (j + 1) : (j + 7);
        __half2 lo = __hmax2(qlo[kp], mn[ks]);
        __half2 hi = __hmin2(qhi[kp], mx[ks]);
        __half2 mi = __hmax2(qa[kp], __hmin2(md[ks], qb[kp]));
        __half2 m  = med3h2(lo, mi, hi);
        float2 f = __half22float2(m);
        r0[j] = f.x;
        r1[j] = f.y;
    }
    float4* po0 = reinterpret_cast<float4*>(o);
    float4* po1 = reinterpret_cast<float4*>(o + ROW);
    __stcs(po0 + 0, make_float4(r0[0], r0[1], r0[2], r0[3]));
    __stcs(po0 + 1, make_float4(r0[4], r0[5], r0[6], r0[7]));
    __stcs(po1 + 0, make_float4(r1[0], r1[1], r1[2], r1[3]));
    __stcs(po1 + 1, make_float4(r1[4], r1[5], r1[6], r1[7]));
}

// ======================= interior kernel (no remap) =======================
__global__ void __launch_bounds__(BLOCK, 8)
median3x3_int_kernel(const float* __restrict__ in, float* __restrict__ out) {
    int tid = blockIdx.x * BLOCK + threadIdx.x;
    int wc0  = ((tid % TPR_I) + 1) * EPT;     // 8 .. ROW-16
    int rest = tid / TPR_I;
    int g    = rest % GROUPS;
    int b    = rest / GROUPS;
    int h0   = g * (2 * PPT);
    int base = wc0 - 4;

    const float* img = in + (int64_t)b * IMG;
    float* o = out + (int64_t)b * IMG + (int64_t)h0 * ROW + wc0;

    __half2 zA[15], zB[15];
    float4 tA[4], tB[4];

    // ---- prologue: pair 0 from rows h0-1..h0+2; leaves z-state in zA ----
    {
        __half2 x[15], y[15];
        float wa[16], wb[16];
        load_raw(img + (int64_t)max(h0 - 1, 0) * ROW, base, tA);
        load_raw(img + (int64_t)h0 * ROW,             base, tB);
        to_arr(tA, wa);
        to_arr(tB, wb);
        #pragma unroll
        for (int k = 1; k <= 14; k++) x[k] = __floats2half2_rn(wa[k], wb[k]);   // (h-1|h)
        load_raw(img + (int64_t)(h0 + 1) * ROW, base, tA);
        to_arr(tA, wa);                                                         // row h+1
        #pragma unroll
        for (int k = 1; k <= 14; k++) y[k] = __floats2half2_rn(wb[k], wa[k]);   // (h|h+1)
        load_raw(img + (int64_t)(h0 + 2) * ROW, base, tB);
        to_arr(tB, wb);                                                         // row h+2
        #pragma unroll
        for (int k = 1; k <= 14; k++) zA[k] = __floats2half2_rn(wa[k], wb[k]);  // (h+1|h+2)

        load_raw(img + (int64_t)(h0 + 3) * ROW, base, tA);
        load_raw(img + (int64_t)(h0 + 4) * ROW, base, tB);

        process_store(x, y, zA, o);
        o += 2 * ROW;
    }

    auto step = [&](const __half2* zin, __half2* zout, int i) {
        float w1[16], w2[16];
        to_arr(tA, w1);
        to_arr(tB, w2);
        __half2 yn[15];
        #pragma unroll
        for (int k = 1; k <= 14; k++) {
            zout[k] = __floats2half2_rn(w1[k], w2[k]);   // (h+1 | h+2)
            yn[k]   = prmt_h2(zin[k], zout[k]);          // (h   | h+1)
        }
        if (i < PPT - 1) {
            int hn = h0 + 2 * i + 2;
            load_raw(img + (int64_t)(hn + 1) * ROW,           base, tA);
            load_raw(img + (int64_t)min(hn + 2, H - 1) * ROW, base, tB);
        }
        process_store(zin, yn, zout, o);
        o += 2 * ROW;
    };

    step(zA, zB, 1);
    step(zB, zA, 2);
    step(zA, zB, 3);
    step(zB, zA, 4);
    step(zA, zB, 5);
    step(zB, zA, 6);
    step(zA, zB, 7);
}

// ======================== edge kernel (2 slots/row) ========================
__global__ void __launch_bounds__(BLOCK, 8)
median3x3_edge_kernel(const float* __restrict__ in, float* __restrict__ out) {
    int tid = blockIdx.x * BLOCK + threadIdx.x;
    if (tid >= NTH_E) return;
    int slot = tid & 1;                       // 0 -> wc0=0, 1 -> wc0=ROW-8
    int rest = tid >> 1;
    int g    = rest % GROUPS;
    int b    = rest / GROUPS;
    int h0   = g * (2 * PPT);

    int mode = slot ? 2 : 1;
    int wc0  = slot ? (ROW - EPT) : 0;
    int base = slot ? (ROW - 16) : 0;

    const float* img = in + (int64_t)b * IMG;
    float* o = out + (int64_t)b * IMG + (int64_t)h0 * ROW + wc0;

    __half2 zA[15], zB[15];
    float4 tA[4], tB[4];

    {
        __half2 x[15], y[15];
        float wa[16], wb[16];
        load_raw(img + (int64_t)max(h0 - 1, 0) * ROW, base, tA);
        load_raw(img + (int64_t)h0 * ROW,             base, tB);
        remap(tA, mode, wa);
        remap(tB, mode, wb);
        #pragma unroll
        for (int k = 1; k <= 14; k++) x[k] = __floats2half2_rn(wa[k], wb[k]);
        load_raw(img + (int64_t)(h0 + 1) * ROW, base, tA);
        remap(tA, mode, wa);
        #pragma unroll
        for (int k = 1; k <= 14; k++) y[k] = __floats2half2_rn(wb[k], wa[k]);
        load_raw(img + (int64_t)(h0 + 2) * ROW, base, tB);
        remap(tB, mode, wb);
        #pragma unroll
        for (int k = 1; k <= 14; k++) zA[k] = __floats2half2_rn(wa[k], wb[k]);

        load_raw(img + (int64_t)(h0 + 3) * ROW, base, tA);
        load_raw(img + (int64_t)(h0 + 4) * ROW, base, tB);

        process_store(x, y, zA, o);
        o += 2 * ROW;
    }

    auto step = [&](const __half2* zin, __half2* zout, int i) {
        float w1[16], w2[16];
        remap(tA, mode, w1);
        remap(tB, mode, w2);
        __half2 yn[15];
        #pragma unroll
        for (int k = 1; k <= 14; k++) {
            zout[k] = __floats2half2_rn(w1[k], w2[k]);
            yn[k]   = prmt_h2(zin[k], zout[k]);
        }
        if (i < PPT - 1) {
            int hn = h0 + 2 * i + 2;
            load_raw(img + (int64_t)(hn + 1) * ROW,           base, tA);
            load_raw(img + (int64_t)min(hn + 2, H - 1) * ROW, base, tB);
        }
        process_store(zin, yn, zout, o);
        o += 2 * ROW;
    };

    step(zA, zB, 1);
    step(zB, zA, 2);
    step(zA, zB, 3);
    step(zB, zA, 4);
    step(zA, zB, 5);
    step(zB, zA, 6);
    step(zA, zB, 7);
}

extern "C" void kernel_launch(void* const* d_in, const int* in_sizes, int n_in,
                              void* d_out, int out_size) {
    const float* in = (const float*)d_in[0];
    float* out = (float*)d_out;
    median3x3_edge_kernel<<<(NTH_E + BLOCK - 1) / BLOCK, BLOCK>>>(in, out); // 32 blocks
    median3x3_int_kernel<<<NTH_I / BLOCK, BLOCK>>>(in, out);                // 3040 blocks
}

// round 11
// speedup vs baseline: 1.0389x; 1.0389x over previous
#include <cuda_runtime.h>
#include <cuda_fp16.h>
#include <cstdint>

// Input [32, 512, 512, 3] float32 NHWC, 3x3 median, replicate border.
constexpr int Bn  = 32;
constexpr int H   = 512;
constexpr int W   = 512;
constexpr int C   = 3;
constexpr int ROW = W * C;             // 1536 floats per image row
constexpr int IMG = H * ROW;
constexpr int EPT = 8;                 // wc outputs per thread per row
constexpr int TPR = ROW / EPT;         // 192 slots per row
constexpr int PPT = 8;                 // row-pairs per thread (16 output rows)
constexpr int GROUPS = (H / 2) / PPT;  // 32 pair-groups per image
constexpr int BLOCK = 64;

constexpr int TPR_I   = TPR - 2;               // 190 interior slots per row
constexpr int NTH_I   = Bn * GROUPS * TPR_I;   // 194,560
constexpr int NBLK_I  = NTH_I / BLOCK;         // 3040 (divides exactly)
constexpr int NTH_E   = Bn * GROUPS * 2;       // 2,048 edge threads
constexpr int NBLK_E  = NTH_E / BLOCK;         // 32
constexpr int NBLK    = NBLK_I + NBLK_E;       // 3072

__device__ __forceinline__ __half2 med3h2(__half2 a, __half2 b, __half2 c) {
    __half2 mn = __hmin2(a, b);
    __half2 mx = __hmax2(a, b);
    return __hmax2(mn, __hmin2(mx, c));
}
// (a.high16 | b.low16) — one PRMT
__device__ __forceinline__ __half2 prmt_h2(__half2 a, __half2 b) {
    unsigned int au = *reinterpret_cast<unsigned int*>(&a);
    unsigned int bu = *reinterpret_cast<unsigned int*>(&b);
    unsigned int r  = __byte_perm(au, bu, 0x5432);
    return *reinterpret_cast<__half2*>(&r);
}

__device__ __forceinline__ void load_raw(const float* __restrict__ r, int base,
                                         float4 t[4]) {
    const float4* p = reinterpret_cast<const float4*>(r + base);
    t[0] = p[0]; t[1] = p[1]; t[2] = p[2]; t[3] = p[3];
}
__device__ __forceinline__ void to_arr(const float4 t4[4], float w[16]) {
    w[0]=t4[0].x; w[1]=t4[0].y; w[2]=t4[0].z; w[3]=t4[0].w;
    w[4]=t4[1].x; w[5]=t4[1].y; w[6]=t4[1].z; w[7]=t4[1].w;
    w[8]=t4[2].x; w[9]=t4[2].y; w[10]=t4[2].z; w[11]=t4[2].w;
    w[12]=t4[3].x; w[13]=t4[3].y; w[14]=t4[3].z; w[15]=t4[3].w;
}
// Edge-replicate remap (edge blocks only).
__device__ __forceinline__ void remap(const float4 t4[4], int mode, float w[16]) {
    float t[16];
    to_arr(t4, t);
    if (mode == 1) {
        w[0] = t[0]; w[1] = t[0]; w[2] = t[1]; w[3] = t[2];
        #pragma unroll
        for (int k = 4; k < 16; k++) w[k] = t[k - 4];
    } else {
        #pragma unroll
        for (int k = 0; k < 12; k++) w[k] = t[k + 4];
        w[12] = t[13]; w[13] = t[14]; w[14] = t[15]; w[15] = t[15];
    }
}

// Column sorts + pair-shared horizontal combine + streaming store of one row pair.
__device__ __forceinline__ void process_store(const __half2* x, const __half2* y,
                                              const __half2* z, float* o) {
    __half2 mn[15], md[15], mx[15];
    #pragma unroll
    for (int k = 1; k <= 14; k++) {
        __half2 lo2 = __hmin2(y[k], z[k]);
        __half2 hi2 = __hmax2(y[k], z[k]);
        mn[k] = __hmin2(x[k], lo2);
        mx[k] = __hmax2(x[k], hi2);
        md[k] = __hmax2(lo2, __hmin2(x[k], hi2));
    }
    __half2 qlo[9], qhi[9], qa[9], qb[9];
    #pragma unroll
    for (int k = 4; k <= 8; k++) {
        qlo[k] = __hmax2(mn[k], mn[k + 3]);
        qhi[k] = __hmin2(mx[k], mx[k + 3]);
        qa[k]  = __hmin2(md[k], md[k + 3]);
        qb[k]  = __hmax2(md[k], md[k + 3]);
    }
    float r0[EPT], r1[EPT];
    #pragma unroll
    for (int j = 0; j < EPT; j++) {
        int kp = (j < 4) ? (j + 4) : (j + 1);
        int ks = (j < 4) ? (j + 1) : (j + 7);
        __half2 lo = __hmax2(qlo[kp], mn[ks]);
        __half2 hi = __hmin2(qhi[kp], mx[ks]);
        __half2 mi = __hmax2(qa[kp], __hmin2(md[ks], qb[kp]));
        __half2 m  = med3h2(lo, mi, hi);
        float2 f = __half22float2(m);
        r0[j] = f.x;
        r1[j] = f.y;
    }
    float4* po0 = reinterpret_cast<float4*>(o);
    float4* po1 = reinterpret_cast<float4*>(o + ROW);
    __stcs(po0 + 0, make_float4(r0[0], r0[1], r0[2], r0[3]));
    __stcs(po0 + 1, make_float4(r0[4], r0[5], r0[6], r0[7]));
    __stcs(po1 + 0, make_float4(r1[0], r1[1], r1[2], r1[3]));
    __stcs(po1 + 1, make_float4(r1[4], r1[5], r1[6], r1[7]));
}

// -------- interior path: no remap anywhere --------
__device__ __forceinline__ void run_interior(const float* __restrict__ in,
                                             float* __restrict__ out, int tid) {
    int wc0  = ((tid % TPR_I) + 1) * EPT;     // 8 .. ROW-16
    int rest = tid / TPR_I;
    int g    = rest % GROUPS;
    int b    = rest / GROUPS;
    int h0   = g * (2 * PPT);
    int base = wc0 - 4;

    const float* img = in + (int64_t)b * IMG;
    float* o = out + (int64_t)b * IMG + (int64_t)h0 * ROW + wc0;

    __half2 zA[15], zB[15];
    float4 tA[4], tB[4];
    {
        __half2 x[15], y[15];
        float wa[16], wb[16];
        load_raw(img + (int64_t)max(h0 - 1, 0) * ROW, base, tA);
        load_raw(img + (int64_t)h0 * ROW,             base, tB);
        to_arr(tA, wa);
        to_arr(tB, wb);
        #pragma unroll
        for (int k = 1; k <= 14; k++) x[k] = __floats2half2_rn(wa[k], wb[k]);   // (h-1|h)
        load_raw(img + (int64_t)(h0 + 1) * ROW, base, tA);
        to_arr(tA, wa);
        #pragma unroll
        for (int k = 1; k <= 14; k++) y[k] = __floats2half2_rn(wb[k], wa[k]);   // (h|h+1)
        load_raw(img + (int64_t)(h0 + 2) * ROW, base, tB);
        to_arr(tB, wb);
        #pragma unroll
        for (int k = 1; k <= 14; k++) zA[k] = __floats2half2_rn(wa[k], wb[k]);  // (h+1|h+2)

        load_raw(img + (int64_t)(h0 + 3) * ROW, base, tA);
        load_raw(img + (int64_t)(h0 + 4) * ROW, base, tB);

        process_store(x, y, zA, o);
        o += 2 * ROW;
    }
    auto step = [&](const __half2* zin, __half2* zout, int i) {
        float w1[16], w2[16];
        to_arr(tA, w1);
        to_arr(tB, w2);
        __half2 yn[15];
        #pragma unroll
        for (int k = 1; k <= 14; k++) {
            zout[k] = __floats2half2_rn(w1[k], w2[k]);
            yn[k]   = prmt_h2(zin[k], zout[k]);
        }
        if (i < PPT - 1) {
            int hn = h0 + 2 * i + 2;
            load_raw(img + (int64_t)(hn + 1) * ROW,           base, tA);
            load_raw(img + (int64_t)min(hn + 2, H - 1) * ROW, base, tB);
        }
        process_store(zin, yn, zout, o);
        o += 2 * ROW;
    };
    step(zA, zB, 1);
    step(zB, zA, 2);
    step(zA, zB, 3);
    step(zB, zA, 4);
    step(zA, zB, 5);
    step(zB, zA, 6);
    step(zA, zB, 7);
}

// -------- edge path: remap at consume time --------
__device__ __forceinline__ void run_edge(const float* __restrict__ in,
                                         float* __restrict__ out, int tid) {
    int slot = tid & 1;                       // 0 -> wc0=0, 1 -> wc0=ROW-8
    int rest = tid >> 1;
    int g    = rest % GROUPS;
    int b    = rest / GROUPS;
    int h0   = g * (2 * PPT);

    int mode = slot ? 2 : 1;
    int wc0  = slot ? (ROW - EPT) : 0;
    int base = slot ? (ROW - 16) : 0;

    const float* img = in + (int64_t)b * IMG;
    float* o = out + (int64_t)b * IMG + (int64_t)h0 * ROW + wc0;

    __half2 zA[15], zB[15];
    float4 tA[4], tB[4];
    {
        __half2 x[15], y[15];
        float wa[16], wb[16];
        load_raw(img + (int64_t)max(h0 - 1, 0) * ROW, base, tA);
        load_raw(img + (int64_t)h0 * ROW,             base, tB);
        remap(tA, mode, wa);
        remap(tB, mode, wb);
        #pragma unroll
        for (int k = 1; k <= 14; k++) x[k] = __floats2half2_rn(wa[k], wb[k]);
        load_raw(img + (int64_t)(h0 + 1) * ROW, base, tA);
        remap(tA, mode, wa);
        #pragma unroll
        for (int k = 1; k <= 14; k++) y[k] = __floats2half2_rn(wb[k], wa[k]);
        load_raw(img + (int64_t)(h0 + 2) * ROW, base, tB);
        remap(tB, mode, wb);
        #pragma unroll
        for (int k = 1; k <= 14; k++) zA[k] = __floats2half2_rn(wa[k], wb[k]);

        load_raw(img + (int64_t)(h0 + 3) * ROW, base, tA);
        load_raw(img + (int64_t)(h0 + 4) * ROW, base, tB);

        process_store(x, y, zA, o);
        o += 2 * ROW;
    }
    auto step = [&](const __half2* zin, __half2* zout, int i) {
        float w1[16], w2[16];
        remap(tA, mode, w1);
        remap(tB, mode, w2);
        __half2 yn[15];
        #pragma unroll
        for (int k = 1; k <= 14; k++) {
            zout[k] = __floats2half2_rn(w1[k], w2[k]);
            yn[k]   = prmt_h2(zin[k], zout[k]);
        }
        if (i < PPT - 1) {
            int hn = h0 + 2 * i + 2;
            load_raw(img + (int64_t)(hn + 1) * ROW,           base, tA);
            load_raw(img + (int64_t)min(hn + 2, H - 1) * ROW, base, tB);
        }
        process_store(zin, yn, zout, o);
        o += 2 * ROW;
    };
    step(zA, zB, 1);
    step(zB, zA, 2);
    step(zA, zB, 3);
    step(zB, zA, 4);
    step(zA, zB, 5);
    step(zB, zA, 6);
    step(zA, zB, 7);
}

// Single launch; block-uniform interior/edge split (no intra-warp divergence).
__global__ void __launch_bounds__(BLOCK, 8)
median3x3_fused_kernel(const float* __restrict__ in, float* __restrict__ out) {
    if (blockIdx.x < NBLK_I) {
        int tid = blockIdx.x * BLOCK + threadIdx.x;
        run_interior(in, out, tid);
    } else {
        int tid = (blockIdx.x - NBLK_I) * BLOCK + threadIdx.x;
        run_edge(in, out, tid);
    }
}

extern "C" void kernel_launch(void* const* d_in, const int* in_sizes, int n_in,
                              void* d_out, int out_size) {
    const float* in = (const float*)d_in[0];
    float* out = (float*)d_out;
    median3x3_fused_kernel<<<NBLK, BLOCK>>>(in, out);   // 3072 blocks
}

// round 12
// speedup vs baseline: 1.2808x; 1.2329x over previous
#include <cuda_runtime.h>
#include <cuda_fp16.h>
#include <cstdint>

// Input [32, 512, 512, 3] float32 NHWC, 3x3 median, replicate border.
constexpr int Bn  = 32;
constexpr int H   = 512;
constexpr int W   = 512;
constexpr int C   = 3;
constexpr int ROW = W * C;             // 1536 floats per image row
constexpr int IMG = H * ROW;
constexpr int EPT = 8;                 // wc outputs per thread per row
constexpr int TPR = ROW / EPT;         // 192
constexpr int PPT = 8;                 // row-pairs per thread (16 output rows)
constexpr int GROUPS = (H / 2) / PPT;  // 32 pair-groups per image
constexpr int NTH = Bn * GROUPS * TPR; // 196,608 threads
constexpr int BLOCK = 32;              // one warp per block: finest CTA granularity

__device__ __forceinline__ __half2 med3h2(__half2 a, __half2 b, __half2 c) {
    __half2 mn = __hmin2(a, b);
    __half2 mx = __hmax2(a, b);
    return __hmax2(mn, __hmin2(mx, c));
}
// (a.high16 | b.low16) — one PRMT
__device__ __forceinline__ __half2 prmt_h2(__half2 a, __half2 b) {
    unsigned int au = *reinterpret_cast<unsigned int*>(&a);
    unsigned int bu = *reinterpret_cast<unsigned int*>(&b);
    unsigned int r  = __byte_perm(au, bu, 0x5432);
    return *reinterpret_cast<__half2*>(&r);
}

// Raw vectorized window load (prefetch half): 4x LDG.128, no remap yet.
__device__ __forceinline__ void load_raw(const float* __restrict__ r, int base,
                                         float4 t[4]) {
    const float4* p = reinterpret_cast<const float4*>(r + base);
    t[0] = p[0]; t[1] = p[1]; t[2] = p[2]; t[3] = p[3];
}
// Register remap (edge replicate) applied at consume time.
__device__ __forceinline__ void remap(const float4 t4[4], int mode, float w[16]) {
    float t[16] = {t4[0].x, t4[0].y, t4[0].z, t4[0].w,
                   t4[1].x, t4[1].y, t4[1].z, t4[1].w,
                   t4[2].x, t4[2].y, t4[2].z, t4[2].w,
                   t4[3].x, t4[3].y, t4[3].z, t4[3].w};
    if (mode == 0) {
        #pragma unroll
        for (int k = 0; k < 16; k++) w[k] = t[k];
    } else if (mode == 1) {
        w[0] = t[0]; w[1] = t[0]; w[2] = t[1]; w[3] = t[2];
        #pragma unroll
        for (int k = 4; k < 16; k++) w[k] = t[k - 4];
    } else {
        #pragma unroll
        for (int k = 0; k < 12; k++) w[k] = t[k + 4];
        w[12] = t[13]; w[13] = t[14]; w[14] = t[15]; w[15] = t[15];
    }
}

// Column sorts + pair-shared horizontal combine + streaming store of one row pair.
__device__ __forceinline__ void process_store(const __half2* x, const __half2* y,
                                              const __half2* z, float* o) {
    __half2 mn[15], md[15], mx[15];
    #pragma unroll
    for (int k = 1; k <= 14; k++) {
        __half2 lo2 = __hmin2(y[k], z[k]);
        __half2 hi2 = __hmax2(y[k], z[k]);
        mn[k] = __hmin2(x[k], lo2);
        mx[k] = __hmax2(x[k], hi2);
        md[k] = __hmax2(lo2, __hmin2(x[k], hi2));
    }
    __half2 qlo[9], qhi[9], qa[9], qb[9];
    #pragma unroll
    for (int k = 4; k <= 8; k++) {
        qlo[k] = __hmax2(mn[k], mn[k + 3]);
        qhi[k] = __hmin2(mx[k], mx[k + 3]);
        qa[k]  = __hmin2(md[k], md[k + 3]);
        qb[k]  = __hmax2(md[k], md[k + 3]);
    }
    float r0[EPT], r1[EPT];
    #pragma unroll
    for (int j = 0; j < EPT; j++) {
        int kp = (j < 4) ? (j + 4) : (j + 1);
        int ks = (j < 4) ? (j + 1) : (j + 7);
        __half2 lo = __hmax2(qlo[kp], mn[ks]);
        __half2 hi = __hmin2(qhi[kp], mx[ks]);
        __half2 mi = __hmax2(qa[kp], __hmin2(md[ks], qb[kp]));
        __half2 m  = med3h2(lo, mi, hi);
        float2 f = __half22float2(m);
        r0[j] = f.x;
        r1[j] = f.y;
    }
    // Streaming stores: output is never re-read; keep L2 for the input rows.
    float4* po0 = reinterpret_cast<float4*>(o);
    float4* po1 = reinterpret_cast<float4*>(o + ROW);
    __stcs(po0 + 0, make_float4(r0[0], r0[1], r0[2], r0[3]));
    __stcs(po0 + 1, make_float4(r0[4], r0[5], r0[6], r0[7]));
    __stcs(po1 + 0, make_float4(r1[0], r1[1], r1[2], r1[3]));
    __stcs(po1 + 1, make_float4(r1[4], r1[5], r1[6], r1[7]));
}

__global__ void __launch_bounds__(BLOCK, 16)
median3x3_b32_kernel(const float* __restrict__ in, float* __restrict__ out) {
    int tid = blockIdx.x * BLOCK + threadIdx.x;
    int wc0  = (tid % TPR) * EPT;
    int rest = tid / TPR;
    int g    = rest % GROUPS;
    int b    = rest / GROUPS;
    int h0   = g * (2 * PPT);

    int mode = (wc0 == 0) ? 1 : ((wc0 == ROW - EPT) ? 2 : 0);
    int base = (mode == 0) ? (wc0 - 4) : ((mode == 1) ? 0 : (ROW - 16));

    const float* img = in + (int64_t)b * IMG;
    float* o = out + (int64_t)b * IMG + (int64_t)h0 * ROW + wc0;

    __half2 zA[15], zB[15];
    float4 tA[4], tB[4];

    // ---- prologue: pair 0 from rows h0-1..h0+2; leaves z-state in zA ----
    {
        __half2 x[15], y[15];
        float wa[16], wb[16];
        load_raw(img + (int64_t)max(h0 - 1, 0) * ROW, base, tA);
        load_raw(img + (int64_t)h0 * ROW,             base, tB);
        remap(tA, mode, wa);
        remap(tB, mode, wb);
        #pragma unroll
        for (int k = 1; k <= 14; k++) x[k] = __floats2half2_rn(wa[k], wb[k]);   // (h-1|h)
        load_raw(img + (int64_t)(h0 + 1) * ROW, base, tA);
        remap(tA, mode, wa);                                                    // row h+1
        #pragma unroll
        for (int k = 1; k <= 14; k++) y[k] = __floats2half2_rn(wb[k], wa[k]);   // (h|h+1)
        load_raw(img + (int64_t)(h0 + 2) * ROW, base, tB);
        remap(tB, mode, wb);                                                    // row h+2
        #pragma unroll
        for (int k = 1; k <= 14; k++) zA[k] = __floats2half2_rn(wa[k], wb[k]);  // (h+1|h+2)

        // prefetch pair 1's rows (h0+3, h0+4) before the heavy compute
        load_raw(img + (int64_t)(h0 + 3) * ROW, base, tA);
        load_raw(img + (int64_t)(h0 + 4) * ROW, base, tB);

        process_store(x, y, zA, o);
        o += 2 * ROW;
    }

    // ---- one march step: consume prefetch into zout, no buffer copies ----
    auto step = [&](const __half2* zin, __half2* zout, int i) {
        float w1[16], w2[16];
        remap(tA, mode, w1);
        remap(tB, mode, w2);
        __half2 yn[15];
        #pragma unroll
        for (int k = 1; k <= 14; k++) {
            zout[k] = __floats2half2_rn(w1[k], w2[k]);   // (h+1 | h+2)
            yn[k]   = prmt_h2(zin[k], zout[k]);          // (h   | h+1)
        }
        // prefetch pair i+1's rows before the median network
        if (i < PPT - 1) {
            int hn = h0 + 2 * i + 2;
            load_raw(img + (int64_t)(hn + 1) * ROW,           base, tA);
            load_raw(img + (int64_t)min(hn + 2, H - 1) * ROW, base, tB);
        }
        process_store(zin, yn, zout, o);
        o += 2 * ROW;
    };

    // ---- pipelined march, ping-pong zA/zB (PPT-1 = 7 steps) ----
    step(zA, zB, 1);
    step(zB, zA, 2);
    step(zA, zB, 3);
    step(zB, zA, 4);
    step(zA, zB, 5);
    step(zB, zA, 6);
    step(zA, zB, 7);
}

extern "C" void kernel_launch(void* const* d_in, const int* in_sizes, int n_in,
                              void* d_out, int out_size) {
    const float* in = (const float*)d_in[0];
    float* out = (float*)d_out;
    int blocks = NTH / BLOCK;   // 6144
    median3x3_b32_kernel<<<blocks, BLOCK>>>(in, out);
}